// round 1
// baseline (speedup 1.0000x reference)
#include <cuda_runtime.h>
#include <cuda_bf16.h>

typedef unsigned long long ull;

#define BETA_F   0.99f
#define EPS_V_F  1e-3f

// per-block partial sums for the logp reduction (deterministic 2-pass, no atomics)
__device__ float g_partials[16384];

// ---------- packed f32x2 helpers (FFMA2 path: ptxas never auto-fuses these) ----------
__device__ __forceinline__ ull pack2(float lo, float hi) {
    ull r;
    asm("mov.b64 %0, {%1, %2};" : "=l"(r) : "f"(lo), "f"(hi));
    return r;
}
__device__ __forceinline__ void unpack2(ull v, float& lo, float& hi) {
    asm("mov.b64 {%0, %1}, %2;" : "=f"(lo), "=f"(hi) : "l"(v));
}
__device__ __forceinline__ ull fma2(ull a, ull b, ull c) {
    ull d;
    asm("fma.rn.f32x2 %0, %1, %2, %3;" : "=l"(d) : "l"(a), "l"(b), "l"(c));
    return d;
}
// relu on both halves: 2x FMNMX -> ALU pipe, dual-issues against the FMA pipe
__device__ __forceinline__ ull relu2(ull v) {
    float lo, hi;
    unpack2(v, lo, hi);
    lo = fmaxf(lo, 0.0f);
    hi = fmaxf(hi, 0.0f);
    return pack2(lo, hi);
}

// ---------- per-row epilogue (scalar; MUFU-heavy part is tiny vs the MLP) ----------
__device__ __forceinline__ float row_epilogue(
    float x0, float x1,
    float mu0, float mu1, float l0, float l1,
    float y0, float y1, float e0, float e1,
    const float* __restrict__ wv,   // Wv row-major [2,2]
    float& f0, float& f1)
{
    // Vx = ||x @ Wv||^2 + eps_v ; z@Wv: out0 = z0*Wv[0] + z1*Wv[2], out1 = z0*Wv[1] + z1*Wv[3]
    float u0 = fmaf(x1, wv[2], x0 * wv[0]);
    float u1 = fmaf(x1, wv[3], x0 * wv[1]);
    float vx = fmaf(u1, u1, fmaf(u0, u0, EPS_V_F));
    float m0 = fmaf(mu1, wv[2], mu0 * wv[0]);
    float m1 = fmaf(mu1, wv[3], mu0 * wv[1]);
    float vmu = fmaf(m1, m1, fmaf(m0, m0, EPS_V_F));
    // (b*Vx - relu(b*Vx - Vmu)) / Vmu  ==  min(b*Vx, Vmu) / Vmu
    float bvx = BETA_F * vx;
    float s   = __fdividef(fminf(bvx, vmu), vmu);
    float ms0 = mu0 * s;
    float ms1 = mu1 * s;
    // var = exp(l)  =>  sqrt(var)=exp(0.5 l), 1/var = exp(-l), log(var) = l
    float sd0 = __expf(0.5f * l0);
    float sd1 = __expf(0.5f * l1);
    float iv0 = __expf(-l0);
    float iv1 = __expf(-l1);
    f0 = fmaf(sd0, e0, ms0);
    f1 = fmaf(sd1, e1, ms1);
    float d0 = y0 - ms0;
    float d1 = y1 - ms1;
    // term = d0^2/v0 + l0 + d1^2/v1 + l1   (per-row contribution; const 2*log(2pi) added at end)
    return fmaf(d0 * d0, iv0, fmaf(d1 * d1, iv1, l0 + l1));
}

// ---------- main kernel: 4 rows per thread, rows packed 2-wide in f32x2 ----------
__global__ __launch_bounds__(256) void mdn_kernel(
    const float* __restrict__ x, const float* __restrict__ y, const float* __restrict__ eps,
    const float* __restrict__ W1, const float* __restrict__ b1,
    const float* __restrict__ W2, const float* __restrict__ b2,
    const float* __restrict__ Wv,
    float* __restrict__ out, long long B)
{
    // weights pre-duplicated as (w,w) pairs so LDS feeds FFMA2 operands directly
    __shared__ ulonglong2 sW1[64];   // .x = dup(W1[0][j]), .y = dup(W1[1][j])
    __shared__ ull        sB1[64];   // dup(b1[j])
    __shared__ ulonglong2 sW2a[64];  // {dup(W2[j][0]), dup(W2[j][1])}
    __shared__ ulonglong2 sW2b[64];  // {dup(W2[j][2]), dup(W2[j][3])}
    __shared__ float      sWv[4];
    __shared__ float      sb2[4];
    __shared__ float      swsum[8];

    const int tid = threadIdx.x;
    if (tid < 64) {
        float a = W1[tid];        // W1 is [2,64] row-major
        float b = W1[64 + tid];
        sW1[tid].x = pack2(a, a);
        sW1[tid].y = pack2(b, b);
        float bb = b1[tid];
        sB1[tid] = pack2(bb, bb);
        float4 w2 = reinterpret_cast<const float4*>(W2)[tid];  // W2 is [64,4] row-major
        sW2a[tid].x = pack2(w2.x, w2.x);
        sW2a[tid].y = pack2(w2.y, w2.y);
        sW2b[tid].x = pack2(w2.z, w2.z);
        sW2b[tid].y = pack2(w2.w, w2.w);
    }
    if (tid < 4) { sWv[tid] = Wv[tid]; sb2[tid] = b2[tid]; }
    __syncthreads();

    const long long gid = (long long)blockIdx.x * blockDim.x + tid;
    const long long r0  = gid << 2;   // 4 rows per thread
    float lacc = 0.0f;

    if (r0 + 4 <= B) {
        const float4 xA = *reinterpret_cast<const float4*>(x + (r0 << 1));       // rows r0, r0+1
        const float4 xB = *reinterpret_cast<const float4*>(x + (r0 << 1) + 4);   // rows r0+2, r0+3
        ull x0A = pack2(xA.x, xA.z), x1A = pack2(xA.y, xA.w);
        ull x0B = pack2(xB.x, xB.z), x1B = pack2(xB.y, xB.w);

        ull a0A = pack2(sb2[0], sb2[0]);
        ull a1A = pack2(sb2[1], sb2[1]);
        ull a2A = pack2(sb2[2], sb2[2]);
        ull a3A = pack2(sb2[3], sb2[3]);
        ull a0B = a0A, a1B = a1A, a2B = a2A, a3B = a3A;

        #pragma unroll
        for (int j = 0; j < 64; j++) {
            ulonglong2 w1 = sW1[j];     // LDS.128 broadcast
            ull bb = sB1[j];            // LDS.64 broadcast
            ull tA = fma2(x0A, w1.x, fma2(x1A, w1.y, bb));
            ull tB = fma2(x0B, w1.x, fma2(x1B, w1.y, bb));
            ull hA = relu2(tA);
            ull hB = relu2(tB);
            ulonglong2 wa = sW2a[j];    // LDS.128
            ulonglong2 wb = sW2b[j];    // LDS.128
            a0A = fma2(hA, wa.x, a0A);
            a1A = fma2(hA, wa.y, a1A);
            a2A = fma2(hA, wb.x, a2A);
            a3A = fma2(hA, wb.y, a3A);
            a0B = fma2(hB, wa.x, a0B);
            a1B = fma2(hB, wa.y, a1B);
            a2B = fma2(hB, wb.x, a2B);
            a3B = fma2(hB, wb.y, a3B);
        }

        float mu0[4], mu1[4], lv0[4], lv1[4];
        unpack2(a0A, mu0[0], mu0[1]); unpack2(a0B, mu0[2], mu0[3]);
        unpack2(a1A, mu1[0], mu1[1]); unpack2(a1B, mu1[2], mu1[3]);
        unpack2(a2A, lv0[0], lv0[1]); unpack2(a2B, lv0[2], lv0[3]);
        unpack2(a3A, lv1[0], lv1[1]); unpack2(a3B, lv1[2], lv1[3]);

        const float xs0[4] = {xA.x, xA.z, xB.x, xB.z};
        const float xs1[4] = {xA.y, xA.w, xB.y, xB.w};

        const float4 yA = *reinterpret_cast<const float4*>(y + (r0 << 1));
        const float4 yB = *reinterpret_cast<const float4*>(y + (r0 << 1) + 4);
        const float4 eA = *reinterpret_cast<const float4*>(eps + (r0 << 1));
        const float4 eB = *reinterpret_cast<const float4*>(eps + (r0 << 1) + 4);
        const float ys0[4] = {yA.x, yA.z, yB.x, yB.z};
        const float ys1[4] = {yA.y, yA.w, yB.y, yB.w};
        const float es0[4] = {eA.x, eA.z, eB.x, eB.z};
        const float es1[4] = {eA.y, eA.w, eB.y, eB.w};

        float f0[4], f1[4];
        #pragma unroll
        for (int r = 0; r < 4; r++) {
            lacc += row_epilogue(xs0[r], xs1[r], mu0[r], mu1[r], lv0[r], lv1[r],
                                 ys0[r], ys1[r], es0[r], es1[r], sWv, f0[r], f1[r]);
        }

        float4 oA = make_float4(f0[0], f1[0], f0[1], f1[1]);
        float4 oB = make_float4(f0[2], f1[2], f0[3], f1[3]);
        *reinterpret_cast<float4*>(out + (r0 << 1))     = oA;
        *reinterpret_cast<float4*>(out + (r0 << 1) + 4) = oB;
    } else if (r0 < B) {
        // rare tail path (B not a multiple of 4): plain scalar, reads global weights
        for (long long r = r0; r < B; ++r) {
            float x0 = x[2 * r], x1 = x[2 * r + 1];
            float acc0 = b2[0], acc1 = b2[1], acc2 = b2[2], acc3 = b2[3];
            for (int j = 0; j < 64; j++) {
                float h = fmaxf(fmaf(x0, W1[j], fmaf(x1, W1[64 + j], b1[j])), 0.0f);
                acc0 = fmaf(h, W2[4 * j + 0], acc0);
                acc1 = fmaf(h, W2[4 * j + 1], acc1);
                acc2 = fmaf(h, W2[4 * j + 2], acc2);
                acc3 = fmaf(h, W2[4 * j + 3], acc3);
            }
            float ff0, ff1;
            lacc += row_epilogue(x0, x1, acc0, acc1, acc2, acc3,
                                 y[2 * r], y[2 * r + 1], eps[2 * r], eps[2 * r + 1],
                                 sWv, ff0, ff1);
            out[2 * r]     = ff0;
            out[2 * r + 1] = ff1;
        }
    }

    // block reduction of the logp terms
    #pragma unroll
    for (int off = 16; off > 0; off >>= 1)
        lacc += __shfl_xor_sync(0xFFFFFFFFu, lacc, off);
    const int warp = tid >> 5, lane = tid & 31;
    if (lane == 0) swsum[warp] = lacc;
    __syncthreads();
    if (tid == 0) {
        float s = 0.0f;
        #pragma unroll
        for (int w = 0; w < 8; w++) s += swsum[w];
        g_partials[blockIdx.x] = s;
    }
}

// ---------- final reduction: logp_y = 0.5 * sum(terms) + B * log(2*pi) ----------
__global__ void mdn_reduce(float* __restrict__ out, int nblocks, long long B)
{
    __shared__ double sm[256];
    double s = 0.0;
    for (int i = threadIdx.x; i < nblocks; i += 256)
        s += (double)g_partials[i];
    sm[threadIdx.x] = s;
    __syncthreads();
    for (int off = 128; off > 0; off >>= 1) {
        if (threadIdx.x < off) sm[threadIdx.x] += sm[threadIdx.x + off];
        __syncthreads();
    }
    if (threadIdx.x == 0)
        out[2 * B] = (float)(0.5 * sm[0] + (double)B * 1.8378770664093454836);
}

extern "C" void kernel_launch(void* const* d_in, const int* in_sizes, int n_in,
                              void* d_out, int out_size)
{
    const float* x   = (const float*)d_in[0];
    const float* y   = (const float*)d_in[1];
    const float* eps = (const float*)d_in[2];
    const float* W1  = (const float*)d_in[3];
    const float* b1  = (const float*)d_in[4];
    const float* W2  = (const float*)d_in[5];
    const float* b2  = (const float*)d_in[6];
    const float* Wv  = (const float*)d_in[7];

    const long long B = (long long)in_sizes[0] / 2;
    const long long nthreads = (B + 3) >> 2;
    const int grid = (int)((nthreads + 255) >> 8);   // B=2^21 -> 2048 blocks

    mdn_kernel<<<grid, 256>>>(x, y, eps, W1, b1, W2, b2, Wv, (float*)d_out, B);
    mdn_reduce<<<1, 256>>>((float*)d_out, grid, B);
}